// round 12
// baseline (speedup 1.0000x reference)
#include <cuda_runtime.h>
#include <math.h>

#define BB      32
#define DIMM    4096
#define NH      32
#define NKV     8
#define HD      128
#define TSEQ    2048
#define NSPLIT  16
#define CHUNK   128      /* TSEQ / NSPLIT */
#define NSL     16       /* gemm k-slices */
#define QK_SCALE 0.08838834764831845f  /* 128^-0.5 */

typedef unsigned long long u64;
union U64F2 { u64 u; float2 f; };
union F4U2  { float4 f; u64 u[2]; };   // (x,y) = u[0], (z,w) = u[1]

__device__ __forceinline__ u64 fma2(u64 a, u64 b, u64 c) {
    u64 d;
    asm("fma.rn.f32x2 %0, %1, %2, %3;" : "=l"(d) : "l"(a), "l"(b), "l"(c));
    return d;
}
__device__ __forceinline__ u64 pack2(float lo, float hi) {
    u64 d;
    asm("mov.b64 %0, {%1, %2};" : "=l"(d) : "f"(lo), "f"(hi));
    return d;
}

// ------------------------- scratch (device globals) -------------------------
__device__ float g_q[BB * NH * HD];            // roped Q   [b][h][d]
__device__ float g_k[BB * NKV * HD];           // roped K @ pos 2047 [b][kv][d]
__device__ float g_v[BB * NKV * HD];           // V       @ pos 2047 [b][kv][d]
__device__ float g_att[BB * DIMM];             // attention output [b][h*128+d]
__device__ float g_part[BB * NH * NSPLIT * HD];
__device__ float g_ml[BB * NH * NSPLIT * 2];   // (m, l) per split
__device__ float g_p[BB * NKV * NSPLIT * 4 * CHUNK];  // exp'd probs per split
__device__ float g_pqkv[NSL * 32 * 6144];      // qkv gemm partials [s][m][n]
__device__ float g_pout[NSL * 32 * 4096];      // out gemm partials [s][m][n]

// ---------------------------------------------------------------------------
// GEMM: thread owns one output column; x broadcast from smem (LDS.128);
// w private register stream; fma.rn.f32x2 with free pair formation via
// float4/u64 union. Split-K partials. (unchanged — validated)
// ---------------------------------------------------------------------------
template <int MODE>
__global__ __launch_bounds__(128) void gemm_kernel(
    const float* __restrict__ x,
    const float* __restrict__ wq, const float* __restrict__ wk,
    const float* __restrict__ wv)
{
    __shared__ float4 xs4[32 * 64];   // 32 KB: x slice [m][64 float4]

    const int tid   = threadIdx.x;
    const int slice = blockIdx.y;
    const int n     = blockIdx.x * 128 + tid;
    const int NTOT  = (MODE == 0) ? 6144 : 4096;

    const float* w; int nr;
    if (MODE == 0) {
        if (n < 4096)      { w = wq; nr = n; }
        else if (n < 5120) { w = wk; nr = n - 4096; }
        else               { w = wv; nr = n - 5120; }
    } else { w = wq; nr = n; }

    const float4* wr = (const float4*)(w + (size_t)nr * 4096 + slice * 256);
    const float4* xg = (const float4*)((MODE == 1) ? (const float*)g_att : x);

#pragma unroll
    for (int j = 0; j < 16; j++) {
        int idx = tid + j * 128;
        int m   = idx >> 6;
        int kk  = idx & 63;
        xs4[idx] = xg[m * 1024 + slice * 64 + kk];
    }
    __syncthreads();

    u64 acc[32];
#pragma unroll
    for (int m = 0; m < 32; m++) acc[m] = 0ull;

#pragma unroll 4
    for (int kq = 0; kq < 64; kq++) {
        F4U2 wu; wu.f = wr[kq];
#pragma unroll
        for (int m = 0; m < 32; m++) {
            F4U2 xu; xu.f = xs4[m * 64 + kq];   // broadcast LDS.128
            acc[m] = fma2(xu.u[0], wu.u[0], acc[m]);
            acc[m] = fma2(xu.u[1], wu.u[1], acc[m]);
        }
    }

    float* part = ((MODE == 0) ? g_pqkv : g_pout)
                + (size_t)slice * 32 * NTOT + n;
#pragma unroll
    for (int m = 0; m < 32; m++) {
        U64F2 u; u.u = acc[m];
        part[(size_t)m * NTOT] = u.f.x + u.f.y;
    }
}

// ---------------------------------------------------------------------------
// Epilogue 0: reduce QKV partials + RoPE -> g_q / g_k / g_v. grid (12,32).
// ---------------------------------------------------------------------------
__global__ __launch_bounds__(256) void epi0_kernel(
    const float* __restrict__ fc, const float* __restrict__ fs)
{
    const int m  = blockIdx.y;
    const int np = blockIdx.x * 256 + threadIdx.x;
    const int n0 = np * 2;

    float sx = 0.f, sy = 0.f;
#pragma unroll
    for (int s = 0; s < NSL; s++) {
        float2 v = *(const float2*)&g_pqkv[((size_t)s * 32 + m) * 6144 + n0];
        sx += v.x; sy += v.y;
    }

    if (n0 < 4096) {
        int h = n0 >> 7, d = n0 & 127, i0 = d >> 1;
        float c0 = fc[i0], s0 = fs[i0];
        *(float2*)&g_q[(m * NH + h) * HD + d] =
            make_float2(sx * c0 - sy * s0, sx * s0 + sy * c0);
    } else if (n0 < 5120) {
        int nk = n0 - 4096;
        int h = nk >> 7, d = nk & 127, i0 = d >> 1;
        float c0 = fc[i0], s0 = fs[i0];
        *(float2*)&g_k[(m * NKV + h) * HD + d] =
            make_float2(sx * c0 - sy * s0, sx * s0 + sy * c0);
    } else {
        int nv = n0 - 5120;
        int h = nv >> 7, d = nv & 127;
        *(float2*)&g_v[(m * NKV + h) * HD + d] = make_float2(sx, sy);
    }
}

// ---------------------------------------------------------------------------
// Epilogue 1: reduce out-proj partials -> out. grid (16, 32) x 256.
// ---------------------------------------------------------------------------
__global__ __launch_bounds__(256) void epi1_kernel(float* __restrict__ out)
{
    const int m = blockIdx.y;
    const int n = blockIdx.x * 256 + threadIdx.x;
    float s = 0.f;
#pragma unroll
    for (int sl = 0; sl < NSL; sl++)
        s += g_pout[((size_t)sl * 32 + m) * 4096 + n];
    out[(size_t)m * 4096 + n] = s;
}

// ---------------------------------------------------------------------------
// SCORE pass v4: pv-shaped K stream. Thread = (row r = lane>>2, dquad
// dq = lane&3); warp instruction = 8 rows x 64B contiguous (coalesced).
// Thread accumulates its 32-float stripe of the row for 4 heads with fma2
// (same math density as pv). Reduction: just 2 SHFLs per head over the
// 4 dquads (vs 31-SHFL tree). Q from smem (4-addr broadcast LDS.128).
// Row 127 of the last split reads the roped g_k row via pointer swap.
// 8 warps x 8 rows x 2 passes = 128 rows. No staging, no CTA barrier
// until softmax.
// ---------------------------------------------------------------------------
__global__ __launch_bounds__(256) void score_kernel(
    const float* __restrict__ ck)
{
    __shared__ float4 sq4[4 * 32];         // Q: 4 heads x 32 quads (2 KB)
    __shared__ float  s_sc[4 * CHUNK];
    __shared__ float  s_ml[8];

    const int bid   = blockIdx.x;
    const int split = bid % NSPLIT;
    const int kv    = (bid / NSPLIT) % NKV;
    const int b     = bid / (NSPLIT * NKV);
    const int tid   = threadIdx.x;
    const int lane  = tid & 31;
    const int warp  = tid >> 5;
    const int t0    = split * CHUNK;
    const bool last = (split == NSPLIT - 1);

    // load Q into smem
    if (tid < 128)
        sq4[tid] = ((const float4*)g_q)[(b * NH + kv * 4) * 32 + tid];
    __syncthreads();

    const int rl = lane >> 2;       // row within warp group (0..7)
    const int dq = lane & 3;        // dquad group (0..3)

#pragma unroll
    for (int pass = 0; pass < 2; pass++) {
        const int row = warp * 8 + pass * 64 + rl;
        const float4* krow;
        if (last && row == CHUNK - 1)
            krow = (const float4*)g_k + (b * NKV + kv) * 32;
        else
            krow = (const float4*)ck
                 + (size_t)((b * TSEQ + t0 + row) * NKV + kv) * 32;

        u64 a0 = 0, a1 = 0, a2 = 0, a3 = 0;
#pragma unroll
        for (int j = 0; j < 8; j++) {
            int c = dq + 4 * j;                 // float4 chunk index
            F4U2 ku; ku.f = krow[c];
            F4U2 q0u; q0u.f = sq4[0 * 32 + c];
            F4U2 q1u; q1u.f = sq4[1 * 32 + c];
            F4U2 q2u; q2u.f = sq4[2 * 32 + c];
            F4U2 q3u; q3u.f = sq4[3 * 32 + c];
            a0 = fma2(ku.u[0], q0u.u[0], a0); a0 = fma2(ku.u[1], q0u.u[1], a0);
            a1 = fma2(ku.u[0], q1u.u[0], a1); a1 = fma2(ku.u[1], q1u.u[1], a1);
            a2 = fma2(ku.u[0], q2u.u[0], a2); a2 = fma2(ku.u[1], q2u.u[1], a2);
            a3 = fma2(ku.u[0], q3u.u[0], a3); a3 = fma2(ku.u[1], q3u.u[1], a3);
        }
        U64F2 u0, u1, u2, u3;
        u0.u = a0; u1.u = a1; u2.u = a2; u3.u = a3;
        float s0 = u0.f.x + u0.f.y;
        float s1 = u1.f.x + u1.f.y;
        float s2 = u2.f.x + u2.f.y;
        float s3 = u3.f.x + u3.f.y;
        // reduce over the 4 dquads (lanes differing in bits 0-1)
#pragma unroll
        for (int o = 1; o <= 2; o <<= 1) {
            s0 += __shfl_xor_sync(0xffffffffu, s0, o);
            s1 += __shfl_xor_sync(0xffffffffu, s1, o);
            s2 += __shfl_xor_sync(0xffffffffu, s2, o);
            s3 += __shfl_xor_sync(0xffffffffu, s3, o);
        }
        if (dq == 0) {
            s_sc[0 * CHUNK + row] = s0 * QK_SCALE;
            s_sc[1 * CHUNK + row] = s1 * QK_SCALE;
            s_sc[2 * CHUNK + row] = s2 * QK_SCALE;
            s_sc[3 * CHUNK + row] = s3 * QK_SCALE;
        }
    }
    __syncthreads();

    // ---- split-local softmax (warp r handles head r) ----
    if (warp < 4) {
        float* row = s_sc + warp * CHUNK;
        float v[CHUNK / 32];
        float mx = -1e30f;
#pragma unroll
        for (int j = 0; j < CHUNK / 32; j++) { v[j] = row[lane + 32 * j]; mx = fmaxf(mx, v[j]); }
#pragma unroll
        for (int o = 16; o; o >>= 1) mx = fmaxf(mx, __shfl_xor_sync(0xffffffffu, mx, o));
        float sum = 0.f;
#pragma unroll
        for (int j = 0; j < CHUNK / 32; j++) {
            float p = __expf(v[j] - mx);
            row[lane + 32 * j] = p;
            sum += p;
        }
#pragma unroll
        for (int o = 16; o; o >>= 1) sum += __shfl_xor_sync(0xffffffffu, sum, o);
        if (lane == 0) { s_ml[warp * 2] = mx; s_ml[warp * 2 + 1] = sum; }
    }
    __syncthreads();

    // write exp'd probs + (m,l) to global
    float* gp = g_p + (size_t)bid * 4 * CHUNK;
#pragma unroll
    for (int i = tid; i < 4 * CHUNK; i += 256) gp[i] = s_sc[i];
    if (tid < 8) {
        int r = tid >> 1;
        g_ml[((b * NH + kv * 4 + r) * NSPLIT + split) * 2 + (tid & 1)] = s_ml[tid];
    }
}

// ---------------------------------------------------------------------------
// PV pass: pure V stream, interleaved load+fma2 (roofline-validated).
// ---------------------------------------------------------------------------
__global__ __launch_bounds__(256) void pv_kernel(const float* __restrict__ cv)
{
    __shared__ float  s_sc[4 * CHUNK];
    __shared__ float4 s_red[8 * 4 * 32];   // 16 KB: [pg][h][dquad]

    const int bid   = blockIdx.x;
    const int split = bid % NSPLIT;
    const int kv    = (bid / NSPLIT) % NKV;
    const int b     = bid / (NSPLIT * NKV);
    const int tid   = threadIdx.x;
    const int lane  = tid & 31;
    const int warp  = tid >> 5;
    const int t0    = split * CHUNK;
    const bool last = (split == NSPLIT - 1);
    const int nmain = last ? CHUNK - 1 : CHUNK;

    const float* gp = g_p + (size_t)bid * 4 * CHUNK;
#pragma unroll
    for (int i = tid; i < 4 * CHUNK; i += 256) s_sc[i] = gp[i];
    __syncthreads();

    {
        const int pg = warp;
        const int dq = lane;
        u64 a0l = 0, a0h = 0, a1l = 0, a1h = 0;
        u64 a2l = 0, a2h = 0, a3l = 0, a3h = 0;
        const float4* vb = (const float4*)cv
                         + (size_t)(b * TSEQ + t0) * (NKV * 32) + kv * 32 + dq;
        const float* p0r = s_sc + 0 * CHUNK;
        const float* p1r = s_sc + 1 * CHUNK;
        const float* p2r = s_sc + 2 * CHUNK;
        const float* p3r = s_sc + 3 * CHUNK;
#pragma unroll 8
        for (int i = pg; i < nmain; i += 8) {
            F4U2 vu; vu.f = vb[(size_t)i * (NKV * 32)];
            u64 pp0 = pack2(p0r[i], p0r[i]);
            u64 pp1 = pack2(p1r[i], p1r[i]);
            u64 pp2 = pack2(p2r[i], p2r[i]);
            u64 pp3 = pack2(p3r[i], p3r[i]);
            a0l = fma2(pp0, vu.u[0], a0l); a0h = fma2(pp0, vu.u[1], a0h);
            a1l = fma2(pp1, vu.u[0], a1l); a1h = fma2(pp1, vu.u[1], a1h);
            a2l = fma2(pp2, vu.u[0], a2l); a2h = fma2(pp2, vu.u[1], a2h);
            a3l = fma2(pp3, vu.u[0], a3l); a3h = fma2(pp3, vu.u[1], a3h);
        }
        F4U2 r0, r1, r2, r3;
        r0.u[0] = a0l; r0.u[1] = a0h;
        r1.u[0] = a1l; r1.u[1] = a1h;
        r2.u[0] = a2l; r2.u[1] = a2h;
        r3.u[0] = a3l; r3.u[1] = a3h;
        s_red[(pg * 4 + 0) * 32 + dq] = r0.f;
        s_red[(pg * 4 + 1) * 32 + dq] = r1.f;
        s_red[(pg * 4 + 2) * 32 + dq] = r2.f;
        s_red[(pg * 4 + 3) * 32 + dq] = r3.f;
    }
    __syncthreads();

    if (tid < 128) {
        const int h  = tid >> 5;
        const int dq = tid & 31;
        float4 s = make_float4(0.f, 0.f, 0.f, 0.f);
#pragma unroll
        for (int pg = 0; pg < 8; pg++) {
            float4 t = s_red[(pg * 4 + h) * 32 + dq];
            s.x += t.x; s.y += t.y; s.z += t.z; s.w += t.w;
        }
        if (last) {
            float4 v4 = ((const float4*)g_v)[(b * NKV + kv) * 32 + dq];
            float p = s_sc[h * CHUNK + CHUNK - 1];
            s.x = fmaf(p, v4.x, s.x); s.y = fmaf(p, v4.y, s.y);
            s.z = fmaf(p, v4.z, s.z); s.w = fmaf(p, v4.w, s.w);
        }
        float4* gpart = (float4*)g_part;
        gpart[((size_t)(b * NH + kv * 4 + h) * NSPLIT + split) * 32 + dq] = s;
    }
}

// ---------------------------------------------------------------------------
// Combine split partials (log-sum-exp). Grid = BB*NH/4 blocks x 128
// (warp per head, lane = d-quad, float4 loads). Validated.
// ---------------------------------------------------------------------------
__global__ __launch_bounds__(128) void reduce_kernel()
{
    const int warp = threadIdx.x >> 5;
    const int lane = threadIdx.x & 31;
    const int hg   = blockIdx.x * 4 + warp;   // b*NH + h

    float ms[NSPLIT], ls[NSPLIT];
    float m = -1e30f;
#pragma unroll
    for (int i = 0; i < NSPLIT; i++) {
        ms[i] = g_ml[(hg * NSPLIT + i) * 2];
        ls[i] = g_ml[(hg * NSPLIT + i) * 2 + 1];
        m = fmaxf(m, ms[i]);
    }
    float4 num = make_float4(0.f, 0.f, 0.f, 0.f);
    float den = 0.f;
    const float4* gpart = (const float4*)g_part;
#pragma unroll
    for (int i = 0; i < NSPLIT; i++) {
        float wgt = __expf(ms[i] - m);
        den += wgt * ls[i];
        float4 p = gpart[((size_t)hg * NSPLIT + i) * 32 + lane];
        num.x = fmaf(wgt, p.x, num.x); num.y = fmaf(wgt, p.y, num.y);
        num.z = fmaf(wgt, p.z, num.z); num.w = fmaf(wgt, p.w, num.w);
    }
    const int b = hg >> 5, h = hg & 31;
    float inv = 1.0f / den;
    float4 o = make_float4(num.x * inv, num.y * inv, num.z * inv, num.w * inv);
    ((float4*)g_att)[(b * DIMM + h * HD) / 4 + lane] = o;
}

// ---------------------------------------------------------------------------
extern "C" void kernel_launch(void* const* d_in, const int* in_sizes, int n_in,
                              void* d_out, int out_size)
{
    const float* x  = (const float*)d_in[0];
    const float* fc = (const float*)d_in[1];
    const float* fs = (const float*)d_in[2];
    const float* wq = (const float*)d_in[3];
    const float* wk = (const float*)d_in[4];
    const float* wv = (const float*)d_in[5];
    const float* wo = (const float*)d_in[6];
    const float* ck = (const float*)d_in[7];
    const float* cv = (const float*)d_in[8];
    float* out = (float*)d_out;

    gemm_kernel<0><<<dim3(48, 16), 128>>>(x, wq, wk, wv);
    epi0_kernel<<<dim3(12, 32), 256>>>(fc, fs);
    score_kernel<<<BB * NKV * NSPLIT, 256>>>(ck);
    pv_kernel<<<BB * NKV * NSPLIT, 256>>>(cv);
    reduce_kernel<<<BB * NH / 4, 128>>>();
    gemm_kernel<1><<<dim3(32, 16), 128>>>(nullptr, wo, nullptr, nullptr);
    epi1_kernel<<<dim3(16, 32), 256>>>(out);
}

// round 13
// speedup vs baseline: 1.1755x; 1.1755x over previous
#include <cuda_runtime.h>
#include <math.h>

#define BB      32
#define DIMM    4096
#define NH      32
#define NKV     8
#define HD      128
#define TSEQ    2048
#define NSPLIT  16
#define CHUNK   128      /* TSEQ / NSPLIT */
#define NSL     16       /* gemm k-slices */
#define QK_SCALE 0.08838834764831845f  /* 128^-0.5 */

typedef unsigned long long u64;
union U64F2 { u64 u; float2 f; };
union F4U2  { float4 f; u64 u[2]; };   // (x,y) = u[0], (z,w) = u[1]

__device__ __forceinline__ u64 fma2(u64 a, u64 b, u64 c) {
    u64 d;
    asm("fma.rn.f32x2 %0, %1, %2, %3;" : "=l"(d) : "l"(a), "l"(b), "l"(c));
    return d;
}
__device__ __forceinline__ u64 pack2(float lo, float hi) {
    u64 d;
    asm("mov.b64 %0, {%1, %2};" : "=l"(d) : "f"(lo), "f"(hi));
    return d;
}

// ------------------------- scratch (device globals) -------------------------
__device__ float g_q[BB * NH * HD];            // roped Q   [b][h][d]
__device__ float g_k[BB * NKV * HD];           // roped K @ pos 2047 [b][kv][d]
__device__ float g_v[BB * NKV * HD];           // V       @ pos 2047 [b][kv][d]
__device__ float g_att[BB * DIMM];             // attention output [b][h*128+d]
__device__ float g_part[BB * NH * NSPLIT * HD];
__device__ float g_ml[BB * NH * NSPLIT * 2];   // (m, l) per split
__device__ float g_pqkv[NSL * 32 * 6144];      // qkv gemm partials [s][m][n]
__device__ float g_pout[NSL * 32 * 4096];      // out gemm partials [s][m][n]

// ---------------------------------------------------------------------------
// GEMM: thread owns one output column; x broadcast from smem (LDS.128);
// w private register stream; fma.rn.f32x2 with free pair formation via
// float4/u64 union. Split-K partials. (validated R8-R12)
// ---------------------------------------------------------------------------
template <int MODE>
__global__ __launch_bounds__(128) void gemm_kernel(
    const float* __restrict__ x,
    const float* __restrict__ wq, const float* __restrict__ wk,
    const float* __restrict__ wv)
{
    __shared__ float4 xs4[32 * 64];   // 32 KB: x slice [m][64 float4]

    const int tid   = threadIdx.x;
    const int slice = blockIdx.y;
    const int n     = blockIdx.x * 128 + tid;
    const int NTOT  = (MODE == 0) ? 6144 : 4096;

    const float* w; int nr;
    if (MODE == 0) {
        if (n < 4096)      { w = wq; nr = n; }
        else if (n < 5120) { w = wk; nr = n - 4096; }
        else               { w = wv; nr = n - 5120; }
    } else { w = wq; nr = n; }

    const float4* wr = (const float4*)(w + (size_t)nr * 4096 + slice * 256);
    const float4* xg = (const float4*)((MODE == 1) ? (const float*)g_att : x);

#pragma unroll
    for (int j = 0; j < 16; j++) {
        int idx = tid + j * 128;
        int m   = idx >> 6;
        int kk  = idx & 63;
        xs4[idx] = xg[m * 1024 + slice * 64 + kk];
    }
    __syncthreads();

    u64 acc[32];
#pragma unroll
    for (int m = 0; m < 32; m++) acc[m] = 0ull;

#pragma unroll 4
    for (int kq = 0; kq < 64; kq++) {
        F4U2 wu; wu.f = wr[kq];
#pragma unroll
        for (int m = 0; m < 32; m++) {
            F4U2 xu; xu.f = xs4[m * 64 + kq];   // broadcast LDS.128
            acc[m] = fma2(xu.u[0], wu.u[0], acc[m]);
            acc[m] = fma2(xu.u[1], wu.u[1], acc[m]);
        }
    }

    float* part = ((MODE == 0) ? g_pqkv : g_pout)
                + (size_t)slice * 32 * NTOT + n;
#pragma unroll
    for (int m = 0; m < 32; m++) {
        U64F2 u; u.u = acc[m];
        part[(size_t)m * NTOT] = u.f.x + u.f.y;
    }
}

// ---------------------------------------------------------------------------
// Epilogue 0: reduce QKV partials + RoPE -> g_q / g_k / g_v. grid (12,32).
// ---------------------------------------------------------------------------
__global__ __launch_bounds__(256) void epi0_kernel(
    const float* __restrict__ fc, const float* __restrict__ fs)
{
    const int m  = blockIdx.y;
    const int np = blockIdx.x * 256 + threadIdx.x;
    const int n0 = np * 2;

    float sx = 0.f, sy = 0.f;
#pragma unroll
    for (int s = 0; s < NSL; s++) {
        float2 v = *(const float2*)&g_pqkv[((size_t)s * 32 + m) * 6144 + n0];
        sx += v.x; sy += v.y;
    }

    if (n0 < 4096) {
        int h = n0 >> 7, d = n0 & 127, i0 = d >> 1;
        float c0 = fc[i0], s0 = fs[i0];
        *(float2*)&g_q[(m * NH + h) * HD + d] =
            make_float2(sx * c0 - sy * s0, sx * s0 + sy * c0);
    } else if (n0 < 5120) {
        int nk = n0 - 4096;
        int h = nk >> 7, d = nk & 127, i0 = d >> 1;
        float c0 = fc[i0], s0 = fs[i0];
        *(float2*)&g_k[(m * NKV + h) * HD + d] =
            make_float2(sx * c0 - sy * s0, sx * s0 + sy * c0);
    } else {
        int nv = n0 - 5120;
        int h = nv >> 7, d = nv & 127;
        *(float2*)&g_v[(m * NKV + h) * HD + d] = make_float2(sx, sy);
    }
}

// ---------------------------------------------------------------------------
// Epilogue 1: reduce out-proj partials -> out. grid (16, 32) x 256.
// ---------------------------------------------------------------------------
__global__ __launch_bounds__(256) void epi1_kernel(float* __restrict__ out)
{
    const int m = blockIdx.y;
    const int n = blockIdx.x * 256 + threadIdx.x;
    float s = 0.f;
#pragma unroll
    for (int sl = 0; sl < NSL; sl++)
        s += g_pout[((size_t)sl * 32 + m) * 4096 + n];
    out[(size_t)m * 4096 + n] = s;
}

// ---------------------------------------------------------------------------
// Combined flash-decode (the 233.8us-validated R8 structure).
// Phase 1: warp handles 8 positions/iter — contiguous-row LDG.128 (dense
//   nL=4), 32 dots, 31-SHFL log-halving tree (one value per lane -> STS).
// Phase 3: pv-style fma2 V loop (roofline-validated in isolation).
// Position 2047 sourced from roped g_k/g_v.
// ---------------------------------------------------------------------------
__global__ __launch_bounds__(256) void attn_kernel(
    const float* __restrict__ ck, const float* __restrict__ cv)
{
    __shared__ float  s_sc[4 * CHUNK];
    __shared__ float  s_ml[8];
    __shared__ float4 s_red[8 * 4 * 32];   // 16 KB: [pg][h][dquad]

    const int bid   = blockIdx.x;
    const int split = bid % NSPLIT;
    const int kv    = (bid / NSPLIT) % NKV;
    const int b     = bid / (NSPLIT * NKV);
    const int tid   = threadIdx.x;
    const int lane  = tid & 31;
    const int warp  = tid >> 5;
    const int t0    = split * CHUNK;
    const bool last = (split == NSPLIT - 1);
    const int nmain = last ? CHUNK - 1 : CHUNK;

    // ---- phase 1: scores; warp handles 8 positions per outer iteration ----
    const float4* qg = (const float4*)g_q;
    const int qb = (b * NH + kv * 4) * 32;
    float4 q0 = qg[qb + 0 * 32 + lane];
    float4 q1 = qg[qb + 1 * 32 + lane];
    float4 q2 = qg[qb + 2 * 32 + lane];
    float4 q3 = qg[qb + 3 * 32 + lane];

    const float4* kg = (const float4*)ck
                     + (size_t)(b * TSEQ + t0) * (NKV * 32) + kv * 32 + lane;
#pragma unroll
    for (int base = warp * 8; base < CHUNK; base += 64) {
        float4 k4[8];
#pragma unroll
        for (int j = 0; j < 8; j++)
            k4[j] = kg[(size_t)(base + j) * (NKV * 32)];

        float s[32];
#pragma unroll
        for (int j = 0; j < 8; j++) {
            s[j*4+0] = fmaf(k4[j].x, q0.x, fmaf(k4[j].y, q0.y, fmaf(k4[j].z, q0.z, k4[j].w * q0.w)));
            s[j*4+1] = fmaf(k4[j].x, q1.x, fmaf(k4[j].y, q1.y, fmaf(k4[j].z, q1.z, k4[j].w * q1.w)));
            s[j*4+2] = fmaf(k4[j].x, q2.x, fmaf(k4[j].y, q2.y, fmaf(k4[j].z, q2.z, k4[j].w * q2.w)));
            s[j*4+3] = fmaf(k4[j].x, q3.x, fmaf(k4[j].y, q3.y, fmaf(k4[j].z, q3.z, k4[j].w * q3.w)));
        }
        // log-halving tree: lane l ends holding the full sum of value l
#pragma unroll
        for (int step = 16; step >= 1; step >>= 1) {
            bool hi = (lane & step) != 0;
#pragma unroll
            for (int i = 0; i < step; i++) {
                float a = hi ? s[i] : s[i + step];
                float c = hi ? s[i + step] : s[i];
                s[i] = c + __shfl_xor_sync(0xffffffffu, a, step);
            }
        }
        int j = lane >> 2, h = lane & 3;       // value index = j*4 + h = lane
        int pos = base + j;
        if (pos < nmain)
            s_sc[h * CHUNK + pos] = s[0] * QK_SCALE;
    }
    if (last && warp == 7) {   // position 2047 from roped scratch
        const float4* kg2 = (const float4*)g_k;
        float4 k4 = kg2[(b * NKV + kv) * 32 + lane];
        float s0 = q0.x * k4.x + q0.y * k4.y + q0.z * k4.z + q0.w * k4.w;
        float s1 = q1.x * k4.x + q1.y * k4.y + q1.z * k4.z + q1.w * k4.w;
        float s2 = q2.x * k4.x + q2.y * k4.y + q2.z * k4.z + q2.w * k4.w;
        float s3 = q3.x * k4.x + q3.y * k4.y + q3.z * k4.z + q3.w * k4.w;
#pragma unroll
        for (int o = 16; o; o >>= 1) {
            s0 += __shfl_xor_sync(0xffffffffu, s0, o);
            s1 += __shfl_xor_sync(0xffffffffu, s1, o);
            s2 += __shfl_xor_sync(0xffffffffu, s2, o);
            s3 += __shfl_xor_sync(0xffffffffu, s3, o);
        }
        if (lane == 0) {
            s_sc[0 * CHUNK + CHUNK - 1] = s0 * QK_SCALE;
            s_sc[1 * CHUNK + CHUNK - 1] = s1 * QK_SCALE;
            s_sc[2 * CHUNK + CHUNK - 1] = s2 * QK_SCALE;
            s_sc[3 * CHUNK + CHUNK - 1] = s3 * QK_SCALE;
        }
    }
    __syncthreads();

    // ---- phase 2: local softmax (warp r handles row r) ----
    if (warp < 4) {
        float* row = s_sc + warp * CHUNK;
        float v[CHUNK / 32];
        float mx = -1e30f;
#pragma unroll
        for (int j = 0; j < CHUNK / 32; j++) { v[j] = row[lane + 32 * j]; mx = fmaxf(mx, v[j]); }
#pragma unroll
        for (int o = 16; o; o >>= 1) mx = fmaxf(mx, __shfl_xor_sync(0xffffffffu, mx, o));
        float sum = 0.f;
#pragma unroll
        for (int j = 0; j < CHUNK / 32; j++) {
            float p = __expf(v[j] - mx);
            row[lane + 32 * j] = p;
            sum += p;
        }
#pragma unroll
        for (int o = 16; o; o >>= 1) sum += __shfl_xor_sync(0xffffffffu, sum, o);
        if (lane == 0) { s_ml[warp * 2] = mx; s_ml[warp * 2 + 1] = sum; }
    }
    __syncthreads();

    // ---- phase 3: P @ V — pv-style fma2 stream (roofline-validated) ----
    {
        const int pg = warp;
        const int dq = lane;
        u64 a0l = 0, a0h = 0, a1l = 0, a1h = 0;
        u64 a2l = 0, a2h = 0, a3l = 0, a3h = 0;
        const float4* vb = (const float4*)cv
                         + (size_t)(b * TSEQ + t0) * (NKV * 32) + kv * 32 + dq;
        const float* p0r = s_sc + 0 * CHUNK;
        const float* p1r = s_sc + 1 * CHUNK;
        const float* p2r = s_sc + 2 * CHUNK;
        const float* p3r = s_sc + 3 * CHUNK;
#pragma unroll 8
        for (int i = pg; i < nmain; i += 8) {
            F4U2 vu; vu.f = vb[(size_t)i * (NKV * 32)];
            u64 pp0 = pack2(p0r[i], p0r[i]);
            u64 pp1 = pack2(p1r[i], p1r[i]);
            u64 pp2 = pack2(p2r[i], p2r[i]);
            u64 pp3 = pack2(p3r[i], p3r[i]);
            a0l = fma2(pp0, vu.u[0], a0l); a0h = fma2(pp0, vu.u[1], a0h);
            a1l = fma2(pp1, vu.u[0], a1l); a1h = fma2(pp1, vu.u[1], a1h);
            a2l = fma2(pp2, vu.u[0], a2l); a2h = fma2(pp2, vu.u[1], a2h);
            a3l = fma2(pp3, vu.u[0], a3l); a3h = fma2(pp3, vu.u[1], a3h);
        }
        F4U2 r0, r1, r2, r3;
        r0.u[0] = a0l; r0.u[1] = a0h;
        r1.u[0] = a1l; r1.u[1] = a1h;
        r2.u[0] = a2l; r2.u[1] = a2h;
        r3.u[0] = a3l; r3.u[1] = a3h;
        s_red[(pg * 4 + 0) * 32 + dq] = r0.f;
        s_red[(pg * 4 + 1) * 32 + dq] = r1.f;
        s_red[(pg * 4 + 2) * 32 + dq] = r2.f;
        s_red[(pg * 4 + 3) * 32 + dq] = r3.f;
    }
    __syncthreads();

    // cross-pos-group reduction + last-position term
    if (tid < 128) {
        const int h  = tid >> 5;
        const int dq = tid & 31;
        float4 s = make_float4(0.f, 0.f, 0.f, 0.f);
#pragma unroll
        for (int pg = 0; pg < 8; pg++) {
            float4 t = s_red[(pg * 4 + h) * 32 + dq];
            s.x += t.x; s.y += t.y; s.z += t.z; s.w += t.w;
        }
        if (last) {
            float4 v4 = ((const float4*)g_v)[(b * NKV + kv) * 32 + dq];
            float p = s_sc[h * CHUNK + CHUNK - 1];
            s.x = fmaf(p, v4.x, s.x); s.y = fmaf(p, v4.y, s.y);
            s.z = fmaf(p, v4.z, s.z); s.w = fmaf(p, v4.w, s.w);
        }
        float4* gpart = (float4*)g_part;
        gpart[((size_t)(b * NH + kv * 4 + h) * NSPLIT + split) * 32 + dq] = s;
    }
    if (tid < 8) {
        int r = tid >> 1;
        g_ml[((b * NH + kv * 4 + r) * NSPLIT + split) * 2 + (tid & 1)] = s_ml[tid];
    }
}

// ---------------------------------------------------------------------------
// Combine split partials (log-sum-exp). Grid = BB*NH/4 blocks x 128
// (warp per head, lane = d-quad, float4 loads). Validated R9-R12.
// ---------------------------------------------------------------------------
__global__ __launch_bounds__(128) void reduce_kernel()
{
    const int warp = threadIdx.x >> 5;
    const int lane = threadIdx.x & 31;
    const int hg   = blockIdx.x * 4 + warp;   // b*NH + h

    float ms[NSPLIT], ls[NSPLIT];
    float m = -1e30f;
#pragma unroll
    for (int i = 0; i < NSPLIT; i++) {
        ms[i] = g_ml[(hg * NSPLIT + i) * 2];
        ls[i] = g_ml[(hg * NSPLIT + i) * 2 + 1];
        m = fmaxf(m, ms[i]);
    }
    float4 num = make_float4(0.f, 0.f, 0.f, 0.f);
    float den = 0.f;
    const float4* gpart = (const float4*)g_part;
#pragma unroll
    for (int i = 0; i < NSPLIT; i++) {
        float wgt = __expf(ms[i] - m);
        den += wgt * ls[i];
        float4 p = gpart[((size_t)hg * NSPLIT + i) * 32 + lane];
        num.x = fmaf(wgt, p.x, num.x); num.y = fmaf(wgt, p.y, num.y);
        num.z = fmaf(wgt, p.z, num.z); num.w = fmaf(wgt, p.w, num.w);
    }
    const int b = hg >> 5, h = hg & 31;
    float inv = 1.0f / den;
    float4 o = make_float4(num.x * inv, num.y * inv, num.z * inv, num.w * inv);
    ((float4*)g_att)[(b * DIMM + h * HD) / 4 + lane] = o;
}

// ---------------------------------------------------------------------------
extern "C" void kernel_launch(void* const* d_in, const int* in_sizes, int n_in,
                              void* d_out, int out_size)
{
    const float* x  = (const float*)d_in[0];
    const float* fc = (const float*)d_in[1];
    const float* fs = (const float*)d_in[2];
    const float* wq = (const float*)d_in[3];
    const float* wk = (const float*)d_in[4];
    const float* wv = (const float*)d_in[5];
    const float* wo = (const float*)d_in[6];
    const float* ck = (const float*)d_in[7];
    const float* cv = (const float*)d_in[8];
    float* out = (float*)d_out;

    gemm_kernel<0><<<dim3(48, 16), 128>>>(x, wq, wk, wv);
    epi0_kernel<<<dim3(12, 32), 256>>>(fc, fs);
    attn_kernel<<<BB * NKV * NSPLIT, 256>>>(ck, cv);
    reduce_kernel<<<BB * NH / 4, 128>>>();
    gemm_kernel<1><<<dim3(32, 16), 128>>>(nullptr, wo, nullptr, nullptr);
    epi1_kernel<<<dim3(16, 32), 256>>>(out);
}